// round 15
// baseline (speedup 1.0000x reference)
#include <cuda_runtime.h>
#include <cstdint>

#define GRIDL 256
#define CELLS (130 * 256 * 256)   // coords reach 129
#define GUARD 0x00808080           // guard bits above each 8-bit coord field

// cell -> output row index (out rows are unique cells; every valid target exists)
__device__ int g_rowid[CELLS];

__global__ void scatter_rowid(const int* __restrict__ out_pos, int M) {
    int m = blockIdx.x * blockDim.x + threadIdx.x;
    if (m >= M) return;
    int x = out_pos[3 * m + 0];
    int y = out_pos[3 * m + 1];
    int z = out_pos[3 * m + 2];
    g_rowid[(x << 16) | (y << 8) | z] = m;
}

#define TILE 64

union F4U2 { float4 f; ulonglong2 u; };

__device__ __forceinline__ int tap_off(int t) {
    int di = t / 9;
    int rem = t - di * 9;
    int dj = rem / 3;
    int dk = rem - dj * 3;
    return (di << 16) | (dj << 8) | dk;
}

__global__ __launch_bounds__(256)
void scatter_conv(const float* __restrict__ feat,
                  const int*   __restrict__ in_pos,
                  const float* __restrict__ W,
                  float*       __restrict__ out,
                  int N) {
    __shared__ float fs[TILE * 32];     // feature tile
    __shared__ int   ls[TILE];          // packed lid per point: (x<<16)|(y<<8)|z

    int tid  = threadIdx.x;
    int warp = tid >> 5;
    int lane = tid & 31;

    int base = blockIdx.x * TILE;
    int cnt  = min(TILE, N - base);

    // stage features: contiguous rows (coalesced float4)
    const float4* fsrc = (const float4*)(feat + (size_t)base * 32);
    for (int i = tid; i < cnt * 8; i += 256)
        ((float4*)fs)[i] = __ldg(fsrc + i);

    // stage packed lids
    for (int i = tid; i < cnt; i += 256) {
        int x = in_pos[3 * (base + i) + 0];
        int y = in_pos[3 * (base + i) + 1];
        int z = in_pos[3 * (base + i) + 2];
        ls[i] = (x << 16) | (y << 8) | z;
    }
    __syncthreads();

    // warp w owns taps {w, w+8, w+16, w+24}; process them as 2 pairs sharing
    // one feature-load stream: (w, w+8) then (w+16, w+24 [may not exist])
    #pragma unroll 1
    for (int g = 0; g < 2; g++) {
        int tA = warp + 16 * g;
        int tB = tA + 8;
        bool hasB = tB < 27;            // warp-uniform

        int offA = tap_off(tA);
        int offB = hasB ? tap_off(tB) : 0;

        // hoist weight columns for both taps (coalesced LDG.32 across lanes)
        F4U2 wA[8], wB[8];
        {
            const float* wk = W + tA * 1024 + lane;
            #pragma unroll
            for (int j = 0; j < 8; j++)
                wA[j].f = make_float4(wk[(4 * j + 0) * 32], wk[(4 * j + 1) * 32],
                                      wk[(4 * j + 2) * 32], wk[(4 * j + 3) * 32]);
        }
        if (hasB) {
            const float* wk = W + tB * 1024 + lane;
            #pragma unroll
            for (int j = 0; j < 8; j++)
                wB[j].f = make_float4(wk[(4 * j + 0) * 32], wk[(4 * j + 1) * 32],
                                      wk[(4 * j + 2) * 32], wk[(4 * j + 3) * 32]);
        } else {
            #pragma unroll
            for (int j = 0; j < 8; j++)
                wB[j].f = make_float4(0.f, 0.f, 0.f, 0.f);
        }

        #pragma unroll 2
        for (int n = 0; n < cnt; n++) {
            int lidp = ls[n] | GUARD;                          // broadcast LDS.32
            int dA = lidp - offA;
            int dB = lidp - offB;
            bool vA = (dA & GUARD) == GUARD;
            bool vB = ((dB & GUARD) == GUARD) & hasB;
            int cA = min(dA ^ GUARD, CELLS - 1);
            int cB = min(dB ^ GUARD, CELLS - 1);
            int rA = __ldg(&g_rowid[cA]);
            int rB = __ldg(&g_rowid[cB]);

            unsigned long long aE0 = 0ull, aO0 = 0ull, aE1 = 0ull, aO1 = 0ull;
            const float4* fr = (const float4*)(fs + n * 32);
            #pragma unroll
            for (int j = 0; j < 8; j++) {
                F4U2 v; v.f = fr[j];                           // broadcast LDS.128
                asm("fma.rn.f32x2 %0, %1, %2, %0;" : "+l"(aE0) : "l"(v.u.x), "l"(wA[j].u.x));
                asm("fma.rn.f32x2 %0, %1, %2, %0;" : "+l"(aO0) : "l"(v.u.y), "l"(wA[j].u.y));
                asm("fma.rn.f32x2 %0, %1, %2, %0;" : "+l"(aE1) : "l"(v.u.x), "l"(wB[j].u.x));
                asm("fma.rn.f32x2 %0, %1, %2, %0;" : "+l"(aO1) : "l"(v.u.y), "l"(wB[j].u.y));
            }
            float2 e0 = *reinterpret_cast<float2*>(&aE0);
            float2 o0 = *reinterpret_cast<float2*>(&aO0);
            float2 e1 = *reinterpret_cast<float2*>(&aE1);
            float2 o1 = *reinterpret_cast<float2*>(&aO1);
            float sA = (e0.x + e0.y) + (o0.x + o0.y);
            float sB = (e1.x + e1.y) + (o1.x + o1.y);
            if (vA) atomicAdd(&out[(size_t)rA * 32 + lane], sA);
            if (vB) atomicAdd(&out[(size_t)rB * 32 + lane], sB);
        }
    }
}

extern "C" void kernel_launch(void* const* d_in, const int* in_sizes, int n_in,
                              void* d_out, int out_size) {
    const float* feat    = (const float*)d_in[0];
    const int*   in_pos  = (const int*)d_in[1];
    const int*   out_pos = (const int*)d_in[2];
    const float* W       = (const float*)d_in[3];
    float* out = (float*)d_out;

    int N = in_sizes[0] / 32;
    int M = in_sizes[2] / 3;

    cudaMemsetAsync(d_out, 0, (size_t)out_size * sizeof(float));
    scatter_rowid<<<(M + 255) / 256, 256>>>(out_pos, M);
    scatter_conv<<<(N + TILE - 1) / TILE, 256>>>(feat, in_pos, W, out, N);
}